// round 15
// baseline (speedup 1.0000x reference)
#include <cuda_runtime.h>
#include <cuda_bf16.h>
#include <math.h>

// GAT layer, fully collapsed, as ONE persistent kernel with grid-wide phase
// barriers (monotonic ticket barrier -> safe across graph replays, no reset):
//   phase 0 (64 blocks): s1 = h @ (W a1), s2 = h @ (W a2)
//   phase 1 ( 8 blocks): bucket-structure softmax -> column mass c_j  (R14 body)
//   phase 2 (64 blocks): v[b,:] = sum_j c[b,j] h[b,j,:]
//   phase 3 ( 8 blocks): out[b] = (1/N) * v[b,:] @ W
// Threshold-sum math and exact-compare branch selection unchanged from R14.

#define B 8
#define N 2048
#define FIN 128
#define FOUT 64
#define ALPHA 0.2f
#define NB 1024
#define NBLK 64
#define NT 1024

// dynamic smem (phase 1 layout is the largest):
//   val2,pA2,pB2,val1,pA1,pB1 [N]; binA,binB [NB]; cnt2,cnt1 [NB]; off2,off1 [NB+1]
#define SMEM_DYN (6 * N * 4 + 2 * NB * 4 + 2 * NB * 4 + 2 * (NB + 1) * 4)

__device__ float d_s1[B * N];
__device__ float d_s2[B * N];
__device__ float d_c[B * N];
__device__ float d_v[B * FIN];
__device__ unsigned int d_bar[4];   // monotonic ticket counters (never reset)

__device__ __forceinline__ float leaky(float x) { return x >= 0.f ? x : ALPHA * x; }

__device__ __forceinline__ int binOf(float x, float lo, float scale) {
    float f = (x - lo) * scale;
    f = fminf(fmaxf(f, 0.f), (float)(NB - 1));
    return (int)f;
}

// grid-wide barrier, replay-safe: counters only ever increase; each use adds
// exactly NBLK, so target = (old/NBLK + 1)*NBLK works for every replay.
__device__ __forceinline__ void gsync(unsigned int* ctr) {
    __syncthreads();
    if (threadIdx.x == 0) {
        __threadfence();
        unsigned int old = atomicAdd(ctr, 1u);
        unsigned int target = (old / NBLK + 1u) * NBLK;
        volatile unsigned int* vc = (volatile unsigned int*)ctr;
        while (*vc < target) { }
    }
    __syncthreads();
}

// gather per-bin payload sums, exclusive-scan 1024 bins (1024 threads).
// totals -> bc[4], bc[5]. Caller syncs after.
__device__ __forceinline__ void binscan(
    const float* pA, const float* pB, const int* off,
    float* binA, float* binB, float* wsA, float* wsB, volatile float* bc,
    int tid, int lane, int wid)
{
    int s = off[tid], e = off[tid + 1];
    float sa = 0.f, sb = 0.f;
    for (int p = s; p < e; p++) { sa += pA[p]; sb += pB[p]; }
    float ia = sa, ib = sb;
#pragma unroll
    for (int o = 1; o < 32; o <<= 1) {
        float ay = __shfl_up_sync(0xffffffffu, ia, o);
        float by = __shfl_up_sync(0xffffffffu, ib, o);
        if (lane >= o) { ia += ay; ib += by; }
    }
    if (lane == 31) { wsA[wid] = ia; wsB[wid] = ib; }
    __syncthreads();
    if (wid == 0) {
        float aw = wsA[lane], bw = wsB[lane];
        float awi = aw, bwi = bw;
#pragma unroll
        for (int o = 1; o < 32; o <<= 1) {
            float ay = __shfl_up_sync(0xffffffffu, awi, o);
            float by = __shfl_up_sync(0xffffffffu, bwi, o);
            if (lane >= o) { awi += ay; bwi += by; }
        }
        wsA[lane] = awi - aw; wsB[lane] = bwi - bw;
        if (lane == 31) { bc[4] = awi; bc[5] = bwi; }
    }
    __syncthreads();
    binA[tid] = ia - sa + wsA[wid];
    binB[tid] = ib - sb + wsB[wid];
}

__global__ void __launch_bounds__(NT, 1) k_fused(
    const float* __restrict__ h, const float* __restrict__ W,
    const float* __restrict__ a, float* __restrict__ out)
{
    int tid = threadIdx.x;           // 1024
    int lane = tid & 31, wid = tid >> 5;
    int blk = blockIdx.x;            // 64 blocks

    extern __shared__ __align__(16) char dyn[];

    // ================= PHASE 0: scores (all 64 blocks) =================
    {
        float* su1 = (float*)dyn;            // [128]
        float* su2 = su1 + FIN;              // [128]
        if (tid < 256) {
            int t = tid & 127;
            const float4* W4 = (const float4*)W;
            const float* av = a + ((tid < 128) ? 0 : FOUT);
            float acc = 0.f;
#pragma unroll
            for (int q = 0; q < 16; q++) {
                float4 w = W4[t * 16 + q];
                acc += w.x * av[q * 4] + w.y * av[q * 4 + 1] +
                       w.z * av[q * 4 + 2] + w.w * av[q * 4 + 3];
            }
            if (tid < 128) su1[t] = acc; else su2[t] = acc;
        }
        __syncthreads();

        int c = lane * 4;
        float u1a = su1[c], u1b = su1[c + 1], u1c = su1[c + 2], u1d = su1[c + 3];
        float u2a = su2[c], u2b = su2[c + 1], u2c = su2[c + 2], u2d = su2[c + 3];

        const float4* h4 = (const float4*)h;
        int row0 = blk * 256 + wid * 8;              // 8 rows per warp
#pragma unroll
        for (int g = 0; g < 2; g++) {
            float4 hv[4];
#pragma unroll
            for (int r = 0; r < 4; r++)
                hv[r] = h4[(size_t)(row0 + g * 4 + r) * (FIN / 4) + lane];
#pragma unroll
            for (int r = 0; r < 4; r++) {
                float a1 = hv[r].x * u1a + hv[r].y * u1b + hv[r].z * u1c + hv[r].w * u1d;
                float a2 = hv[r].x * u2a + hv[r].y * u2b + hv[r].z * u2c + hv[r].w * u2d;
#pragma unroll
                for (int o = 16; o; o >>= 1) {
                    a1 += __shfl_xor_sync(0xffffffffu, a1, o);
                    a2 += __shfl_xor_sync(0xffffffffu, a2, o);
                }
                if (lane == 0) {
                    d_s1[row0 + g * 4 + r] = a1;
                    d_s2[row0 + g * 4 + r] = a2;
                }
            }
        }
    }
    gsync(&d_bar[0]);

    // ================= PHASE 1: attn (blocks 0..7) =================
    if (blk < B) {
        int b = blk;
        float* val2 = (float*)dyn;
        float* pA2  = val2 + N;
        float* pB2  = pA2 + N;
        float* val1 = pB2 + N;
        float* pA1  = val1 + N;
        float* pB1  = pA1 + N;
        float* binA = pB1 + N;
        float* binB = binA + NB;
        int*   cnt2 = (int*)(binB + NB);
        int*   cnt1 = cnt2 + NB;
        int*   off2 = cnt1 + NB;
        int*   off1 = off2 + (NB + 1);

        __shared__ float wsA[32], wsB[32];
        __shared__ int   wsI[32], wsJ[32];
        __shared__ float bc[8];

        float rs1[2], rs2[2];
#pragma unroll
        for (int r = 0; r < 2; r++) {
            int i = tid + (r << 10);
            rs1[r] = __ldcg(&d_s1[b * N + i]);
            rs2[r] = __ldcg(&d_s2[b * N + i]);
        }
        if (tid < FIN) d_v[b * FIN + tid] = 0.f;
        cnt2[tid] = 0;
        cnt1[tid] = 0;

        // min/max of s1, s2 (val2[0..127] as scratch)
        {
            float l1 = fminf(rs1[0], rs1[1]), h1 = fmaxf(rs1[0], rs1[1]);
            float l2 = fminf(rs2[0], rs2[1]), h2 = fmaxf(rs2[0], rs2[1]);
#pragma unroll
            for (int o = 16; o; o >>= 1) {
                l1 = fminf(l1, __shfl_xor_sync(0xffffffffu, l1, o));
                h1 = fmaxf(h1, __shfl_xor_sync(0xffffffffu, h1, o));
                l2 = fminf(l2, __shfl_xor_sync(0xffffffffu, l2, o));
                h2 = fmaxf(h2, __shfl_xor_sync(0xffffffffu, h2, o));
            }
            if (lane == 0) {
                val2[wid] = l1; val2[32 + wid] = h1;
                val2[64 + wid] = l2; val2[96 + wid] = h2;
            }
            __syncthreads();
            if (wid == 0) {
                float a0 = val2[lane], a1m = val2[32 + lane];
                float a2m = val2[64 + lane], a3 = val2[96 + lane];
#pragma unroll
                for (int o = 16; o; o >>= 1) {
                    a0  = fminf(a0,  __shfl_xor_sync(0xffffffffu, a0, o));
                    a1m = fmaxf(a1m, __shfl_xor_sync(0xffffffffu, a1m, o));
                    a2m = fminf(a2m, __shfl_xor_sync(0xffffffffu, a2m, o));
                    a3  = fmaxf(a3,  __shfl_xor_sync(0xffffffffu, a3, o));
                }
                if (lane == 0) { bc[0] = a2m; bc[1] = a3; bc[2] = a0; bc[3] = a1m; }
            }
            __syncthreads();
        }

        float lo2 = bc[0], hi2 = bc[1];
        float lo1 = bc[2], hi1 = bc[3];
        float scale2 = (hi2 > lo2) ? ((float)NB / (hi2 - lo2)) : 0.f;
        float scale1 = (hi1 > lo1) ? ((float)NB / (hi1 - lo1)) : 0.f;

        // dual histogram
        int bn2[2], bn1[2], rk2[2], rk1[2];
#pragma unroll
        for (int r = 0; r < 2; r++) {
            bn2[r] = binOf(rs2[r], lo2, scale2);
            rk2[r] = atomicAdd(&cnt2[bn2[r]], 1);
            bn1[r] = binOf(rs1[r], lo1, scale1);
            rk1[r] = atomicAdd(&cnt1[bn1[r]], 1);
        }
        __syncthreads();

        // fused dual exclusive count scan -> off2, off1
        {
            int c2 = cnt2[tid], c1 = cnt1[tid];
            int i2 = c2, i1 = c1;
#pragma unroll
            for (int o = 1; o < 32; o <<= 1) {
                int y2 = __shfl_up_sync(0xffffffffu, i2, o);
                int y1 = __shfl_up_sync(0xffffffffu, i1, o);
                if (lane >= o) { i2 += y2; i1 += y1; }
            }
            if (lane == 31) { wsI[wid] = i2; wsJ[wid] = i1; }
            __syncthreads();
            if (wid == 0) {
                int w2 = wsI[lane], w1 = wsJ[lane];
                int j2 = w2, j1 = w1;
#pragma unroll
                for (int o = 1; o < 32; o <<= 1) {
                    int y2 = __shfl_up_sync(0xffffffffu, j2, o);
                    int y1 = __shfl_up_sync(0xffffffffu, j1, o);
                    if (lane >= o) { j2 += y2; j1 += y1; }
                }
                wsI[lane] = j2 - w2; wsJ[lane] = j1 - w1;
            }
            __syncthreads();
            off2[tid] = i2 - c2 + wsI[wid];
            off1[tid] = i1 - c1 + wsJ[wid];
            if (tid == 0) { off2[NB] = N; off1[NB] = N; }
        }
        __syncthreads();

        // dual scatter
        int p1s[2];
#pragma unroll
        for (int r = 0; r < 2; r++) {
            int p = off2[bn2[r]] + rk2[r];
            val2[p] = rs2[r];
            pA2[p] = __expf(rs2[r]);
            pB2[p] = __expf(ALPHA * rs2[r]);
            int q = off1[bn1[r]] + rk1[r];
            val1[q] = rs1[r];
            p1s[r] = q;
        }
        __syncthreads();

        binscan(pA2, pB2, off2, binA, binB, wsA, wsB, bc, tid, lane, wid);
        __syncthreads();

        // pass-1 queries -> g
        {
            float smax = bc[1], tA = bc[4], tB = bc[5];
#pragma unroll
            for (int r = 0; r < 2; r++) {
                float s1 = rs1[r];
                float t = -s1;
                int qb = binOf(t, lo2, scale2);
                float SA = binA[qb], SB = binB[qb];
                int pe = off2[qb + 1];
                for (int p = off2[qb]; p < pe; p++) {
                    if (val2[p] <= t) { SA += pA2[p]; SB += pB2[p]; }
                }
                float Apos = tA - SA;
                float m = leaky(s1 + smax);
                float e1 = __expf(s1 - m);
                float e2 = __expf(ALPHA * s1 - m);
                float inv = 1.0f / (e1 * Apos + e2 * SB);
                pA1[p1s[r]] = e1 * inv;
                pB1[p1s[r]] = e2 * inv;
            }
        }
        __syncthreads();

        binscan(pA1, pB1, off1, binA, binB, wsA, wsB, bc, tid, lane, wid);
        __syncthreads();

        // pass-2 queries -> c_j
        {
            float tG1 = bc[4], tG2 = bc[5];
#pragma unroll
            for (int r = 0; r < 2; r++) {
                int j = tid + (r << 10);
                float s2 = rs2[r];
                float t = -s2;
                int qb = binOf(t, lo1, scale1);
                float SG1 = binA[qb], SG2 = binB[qb];
                int pe = off1[qb + 1];
                for (int p = off1[qb]; p < pe; p++) {
                    if (val1[p] <= t) { SG1 += pA1[p]; SG2 += pB1[p]; }
                }
                float P = tG1 - SG1;
                float c = __expf(s2) * P + __expf(ALPHA * s2) * SG2;
                d_c[b * N + j] = c;
            }
        }
    }
    gsync(&d_bar[1]);

    // ================= PHASE 2: wsum (all 64 blocks) =================
    {
        float* red = (float*)dyn;            // 32 warps x 128 = 16KB
        int b = blk >> 3, chunk = blk & 7;   // 8 blocks per batch
        const float4* h4 = (const float4*)h;
        size_t base = (size_t)b * N * (FIN / 4);
        int j0 = chunk * 256 + wid * 8;      // 8 rows per warp
        float4 acc = make_float4(0.f, 0.f, 0.f, 0.f);
#pragma unroll
        for (int r = 0; r < 8; r++) {
            int j = j0 + r;
            float cj = __ldcg(&d_c[b * N + j]);
            float4 hv = h4[base + (size_t)j * (FIN / 4) + lane];
            acc.x = fmaf(cj, hv.x, acc.x);
            acc.y = fmaf(cj, hv.y, acc.y);
            acc.z = fmaf(cj, hv.z, acc.z);
            acc.w = fmaf(cj, hv.w, acc.w);
        }
        ((float4*)red)[wid * 32 + lane] = acc;
        __syncthreads();
        if (tid < FIN) {
            float s = 0.f;
#pragma unroll
            for (int w = 0; w < 32; w++) s += red[w * FIN + tid];
            atomicAdd(&d_v[b * FIN + tid], s);
        }
    }
    gsync(&d_bar[2]);

    // ================= PHASE 3: out (blocks 0..7) =================
    if (blk < B) {
        int b = blk;
        float* sv   = (float*)dyn;           // [128]
        float* part = sv + FIN;              // [16][64]
        if (tid < FIN) sv[tid] = __ldcg(&d_v[b * FIN + tid]);
        __syncthreads();
        int f = tid & 63, kg = tid >> 6;     // 16 k-groups of 8
        float acc = 0.f;
#pragma unroll
        for (int q = 0; q < 8; q++) {
            int k = kg * 8 + q;
            acc = fmaf(sv[k], W[k * FOUT + f], acc);
        }
        part[kg * FOUT + f] = acc;
        __syncthreads();
        if (tid < FOUT) {
            float s = 0.f;
#pragma unroll
            for (int g = 0; g < 16; g++) s += part[g * FOUT + tid];
            out[b * FOUT + tid] = s * (1.0f / (float)N);
        }
    }
}

extern "C" void kernel_launch(void* const* d_in, const int* in_sizes, int n_in,
                              void* d_out, int out_size) {
    (void)in_sizes; (void)n_in; (void)out_size;
    const float* h = (const float*)d_in[0];
    const float* W = (const float*)d_in[1];
    const float* a = (const float*)d_in[2];
    float* out = (float*)d_out;

    cudaFuncSetAttribute(k_fused, cudaFuncAttributeMaxDynamicSharedMemorySize, SMEM_DYN);
    k_fused<<<NBLK, NT, SMEM_DYN>>>(h, W, a, out);
}